// round 14
// baseline (speedup 1.0000x reference)
#include <cuda_runtime.h>

// ReNet layer, R13: R12 design (zero-mov FFMA2 via PRE-DUPLICATED x operands)
// with the vertical staging bug fixed (loop, not a single predicated write).
//   Column-pair packing (acc=(zi,zf),(zg,zo)); the broadcast x scalar is
//   stored as (v,v) 8-byte pairs at its source, so the FFMA2 'a' operand
//   comes straight from LDS.128 / LDG.128 - no pack movs in the GEMM.
//   Vertical: duplicated x+h in smem; writes output DUPLICATED to g_v2.
//   Horizontal: x-part (128 of 192 k's) streamed pre-packed from L2 BEFORE
//   the h barrier; only the 64-k h-recurrence lives in smem (duplicated).
// 256 thr = 4 seq-groups x 2 hid-halves, M=8, conflict-free 16B weight LDS,
// 2 group-local named barriers per step.

#define HIDN 64
#define NGC  256
#define BN   16
#define SJ   128
#define NSEQ 32

typedef unsigned long long ull;

// duplicated vertical output: [b][j][i][128 ulls] (ull = (v,v)), 268 MB
__device__ ull g_v2[(size_t)BN * SJ * SJ * 128];

__device__ __forceinline__ ull pack2(float lo, float hi) {
    ull r; asm("mov.b64 %0, {%1, %2};" : "=l"(r) : "f"(lo), "f"(hi)); return r;
}
__device__ __forceinline__ void unpack2(ull v, float& lo, float& hi) {
    asm("mov.b64 {%0, %1}, %2;" : "=f"(lo), "=f"(hi) : "l"(v));
}
__device__ __forceinline__ void ffma2(ull& d, ull a, ull b) {
    asm("fma.rn.f32x2 %0, %1, %2, %0;" : "+l"(d) : "l"(a), "l"(b));
}
__device__ __forceinline__ float sigf(float x)   { return 1.0f / (1.0f + __expf(-x)); }
__device__ __forceinline__ float mytanh(float x) { return 1.0f - 2.0f / (__expf(2.0f * x) + 1.0f); }
__device__ __forceinline__ void bar_grp(int sg) {
    asm volatile("bar.sync %0, 64;" :: "r"(sg + 1) : "memory");
}

// ---------------------------------------------------------------------------
// Vertical pass: DIN=12, K=76 (pad 80). x and h duplicated in smem.
// ---------------------------------------------------------------------------
__global__ void __launch_bounds__(256, 1)
renet_vert(const float* __restrict__ W0, const float* __restrict__ U0, const float* __restrict__ b0,
           const float* __restrict__ W1, const float* __restrict__ U1, const float* __restrict__ b1,
           const float* __restrict__ src, ull* __restrict__ vout)
{
    constexpr int DIN = 12, K = 76, KP = 80;
    extern __shared__ float sm[];
    float* sWU = sm;                         // [KP][NGC] permuted (wi,wf,wg,wo)/hid
    ull*   sX2 = (ull*)(sm + KP * NGC);      // [NSEQ][KP] duplicated (x ++ h ++ pad)
    float* sB  = (float*)(sX2 + NSEQ * KP);  // [NGC]

    const int dir  = blockIdx.x >> 6;
    const int s0   = (blockIdx.x & 63) * NSEQ;
    const int tid  = threadIdx.x;
    const int lane = tid & 31;
    const int wid  = tid >> 5;
    const int hh   = wid & 1;
    const int sg   = wid >> 1;
    const int gtid = tid & 63;
    const int hid  = hh * 32 + lane;

    const float* W  = dir ? W1 : W0;
    const float* U  = dir ? U1 : U0;
    const float* bb = dir ? b1 : b0;

    for (int idx = tid; idx < KP * NGC; idx += 256) {
        int k = idx >> 8, c = idx & 255;
        int g = c >> 6, h = c & 63;
        int pc = (h >> 5) * 128 + (h & 31) * 4 + g;
        float v = (k < DIN) ? W[k * NGC + c]
                 : (k < K)  ? U[(k - DIN) * NGC + c] : 0.0f;
        sWU[k * NGC + pc] = v;
    }
    for (int idx = tid; idx < NGC; idx += 256) sB[idx] = bb[idx];
    for (int idx = tid; idx < NSEQ * (KP - DIN); idx += 256) {
        int s = idx / (KP - DIN), o = idx % (KP - DIN);
        sX2[s * KP + DIN + o] = 0ull;        // h_0 = 0, pad = 0
    }
    __syncthreads();

    ull binit[2];
    binit[0] = pack2(sB[0 * HIDN + hid], sB[1 * HIDN + hid]);
    binit[1] = pack2(sB[2 * HIDN + hid], sB[3 * HIDN + hid]);

    float cst[8];
#pragma unroll
    for (int p = 0; p < 8; p++) cst[p] = 0.0f;

    auto stage_x = [&](int t) {
        const int jin = dir ? (SJ - 1 - t) : t;
        for (int e = gtid; e < 8 * 12; e += 64) {   // FIX: loop, not predicate
            int sl = e / 12, d = e - sl * 12;
            int q = s0 + sg * 8 + sl;
            int b = q >> 7, i = q & 127;
            int pr = d / 6, rm = d - pr * 6;
            int pc = rm / 3, ch = rm - pc * 3;
            float v = src[((b * 256 + (2 * jin + pr)) * 256 + (2 * i + pc)) * 3 + ch];
            sX2[(sg * 8 + sl) * KP + d] = pack2(v, v);
        }
    };
    stage_x(0);

    const ull*   xrow  = sX2 + (sg * 8) * KP;
    const float* wlane = sWU + hh * 128 + lane * 4;

    for (int t = 0; t < SJ; t++) {
        bar_grp(sg);                         // A: x_t staged, h_{t-1} visible

        ull acc[8][2];
#pragma unroll
        for (int m = 0; m < 8; m++) { acc[m][0] = binit[0]; acc[m][1] = binit[1]; }

        ulonglong2 xA[8][2], xB[8][2], wA[4], wB[4];
        auto loadx = [&](ulonglong2 (*xq)[2], int k) {
#pragma unroll
            for (int m = 0; m < 8; m++) {
                xq[m][0] = *(const ulonglong2*)(xrow + m * KP + k);
                xq[m][1] = *(const ulonglong2*)(xrow + m * KP + k + 2);
            }
        };
        auto loadw = [&](ulonglong2* wq, int k) {
#pragma unroll
            for (int kk = 0; kk < 4; kk++)
                wq[kk] = *(const ulonglong2*)(wlane + (k + kk) * NGC);
        };
        auto chunk = [&](const ulonglong2 (*xq)[2], const ulonglong2* wq) {
#pragma unroll
            for (int kk = 0; kk < 4; kk++) {
#pragma unroll
                for (int m = 0; m < 8; m++) {
                    ull xh = (kk & 1) ? xq[m][kk >> 1].y : xq[m][kk >> 1].x;
                    ffma2(acc[m][0], xh, wq[kk].x);   // (zi, zf)
                    ffma2(acc[m][1], xh, wq[kk].y);   // (zg, zo)
                }
            }
        };

        loadx(xA, 0); loadw(wA, 0);
#pragma unroll 1
        for (int k = 0; k < KP; k += 8) {
            loadx(xB, k + 4); loadw(wB, k + 4);
            chunk(xA, wA);
            if (k + 8 < KP) { loadx(xA, k + 8); loadw(wA, k + 8); }
            chunk(xB, wB);
        }

        bar_grp(sg);                         // B: group's reads done

#pragma unroll
        for (int m = 0; m < 8; m++) {
            float zi, zf, zg, zo;
            unpack2(acc[m][0], zi, zf);
            unpack2(acc[m][1], zg, zo);
            float c = sigf(zf) * cst[m] + sigf(zi) * mytanh(zg);
            cst[m] = c;
            float hv = sigf(zo) * mytanh(c);
            ull hd = pack2(hv, hv);

            int s = sg * 8 + m;
            sX2[s * KP + DIN + hid] = hd;

            int q = s0 + s;
            int b = q >> 7, ic = q & 127;
            vout[((size_t)((b * 128 + t) * 128 + ic)) * 128 + dir * 64 + hid] = hd;
        }

        if (t + 1 < SJ) stage_x(t + 1);
    }
}

// ---------------------------------------------------------------------------
// Horizontal pass: K=192. x-part (k<128) streamed pre-packed from gmem BEFORE
// the barrier; h-part (64 k) from duplicated smem after it.
// ---------------------------------------------------------------------------
__global__ void __launch_bounds__(256, 1)
renet_horiz(const float* __restrict__ W0, const float* __restrict__ U0, const float* __restrict__ b0,
            const float* __restrict__ W1, const float* __restrict__ U1, const float* __restrict__ b1,
            const ull* __restrict__ vin, float* __restrict__ out)
{
    constexpr int KW = 128, KT = 192;
    extern __shared__ float sm[];
    float* sWU = sm;                         // [KT][NGC]
    ull*   sH2 = (ull*)(sm + KT * NGC);      // [NSEQ][64] duplicated h
    float* sB  = (float*)(sH2 + NSEQ * 64);  // [NGC]

    const int dir  = blockIdx.x >> 6;
    const int s0   = (blockIdx.x & 63) * NSEQ;
    const int tid  = threadIdx.x;
    const int lane = tid & 31;
    const int wid  = tid >> 5;
    const int hh   = wid & 1;
    const int sg   = wid >> 1;
    const int hid  = hh * 32 + lane;

    const float* W  = dir ? W1 : W0;
    const float* U  = dir ? U1 : U0;
    const float* bb = dir ? b1 : b0;

    for (int idx = tid; idx < KT * NGC; idx += 256) {
        int k = idx >> 8, c = idx & 255;
        int g = c >> 6, h = c & 63;
        int pc = (h >> 5) * 128 + (h & 31) * 4 + g;
        float v = (k < KW) ? W[k * NGC + c] : U[(k - KW) * NGC + c];
        sWU[k * NGC + pc] = v;
    }
    for (int idx = tid; idx < NGC; idx += 256) sB[idx] = bb[idx];
    for (int idx = tid; idx < NSEQ * 64; idx += 256) sH2[idx] = 0ull;
    __syncthreads();

    ull binit[2];
    binit[0] = pack2(sB[0 * HIDN + hid], sB[1 * HIDN + hid]);
    binit[1] = pack2(sB[2 * HIDN + hid], sB[3 * HIDN + hid]);

    float cst[8];
#pragma unroll
    for (int p = 0; p < 8; p++) cst[p] = 0.0f;

    // group's 8 seqs are consecutive j within one b: base + m*16384 ulls
    const int q0 = s0 + sg * 8;
    const int b0i = q0 >> 7, j0 = q0 & 127;
    const ull*   gx    = vin + ((size_t)(b0i * 128 + j0)) * 128 * 128;
    const float* wlane = sWU + hh * 128 + lane * 4;
    const ull*   hrow  = sH2 + (sg * 8) * 64;

    for (int t = 0; t < SJ; t++) {
        const int i = dir ? (SJ - 1 - t) : t;
        const ull* xp = gx + (size_t)i * 128;

        ull acc[8][2];
#pragma unroll
        for (int m = 0; m < 8; m++) { acc[m][0] = binit[0]; acc[m][1] = binit[1]; }

        {   // ---- x-part: k in [0,128) from gmem, no h dependency
            ulonglong2 xA[8][2], xB[8][2], wA[4], wB[4];
            auto loadx = [&](ulonglong2 (*xq)[2], int k) {
#pragma unroll
                for (int m = 0; m < 8; m++) {
                    xq[m][0] = *(const ulonglong2*)(xp + (size_t)m * 16384 + k);
                    xq[m][1] = *(const ulonglong2*)(xp + (size_t)m * 16384 + k + 2);
                }
            };
            auto loadw = [&](ulonglong2* wq, int k) {
#pragma unroll
                for (int kk = 0; kk < 4; kk++)
                    wq[kk] = *(const ulonglong2*)(wlane + (k + kk) * NGC);
            };
            auto chunk = [&](const ulonglong2 (*xq)[2], const ulonglong2* wq) {
#pragma unroll
                for (int kk = 0; kk < 4; kk++) {
#pragma unroll
                    for (int m = 0; m < 8; m++) {
                        ull xh = (kk & 1) ? xq[m][kk >> 1].y : xq[m][kk >> 1].x;
                        ffma2(acc[m][0], xh, wq[kk].x);
                        ffma2(acc[m][1], xh, wq[kk].y);
                    }
                }
            };
            loadx(xA, 0); loadw(wA, 0);
#pragma unroll 1
            for (int k = 0; k < KW; k += 8) {
                loadx(xB, k + 4); loadw(wB, k + 4);
                chunk(xA, wA);
                if (k + 8 < KW) { loadx(xA, k + 8); loadw(wA, k + 8); }
                chunk(xB, wB);
            }
        }

        bar_grp(sg);                         // A: h_{t-1} visible in sH2

        {   // ---- h-part: k in [128,192) from duplicated smem
            ulonglong2 xA[8][2], xB[8][2], wA[4], wB[4];
            auto loadx = [&](ulonglong2 (*xq)[2], int kk2) {
#pragma unroll
                for (int m = 0; m < 8; m++) {
                    xq[m][0] = *(const ulonglong2*)(hrow + m * 64 + kk2);
                    xq[m][1] = *(const ulonglong2*)(hrow + m * 64 + kk2 + 2);
                }
            };
            auto loadw = [&](ulonglong2* wq, int k) {
#pragma unroll
                for (int kk = 0; kk < 4; kk++)
                    wq[kk] = *(const ulonglong2*)(wlane + (k + kk) * NGC);
            };
            auto chunk = [&](const ulonglong2 (*xq)[2], const ulonglong2* wq) {
#pragma unroll
                for (int kk = 0; kk < 4; kk++) {
#pragma unroll
                    for (int m = 0; m < 8; m++) {
                        ull xh = (kk & 1) ? xq[m][kk >> 1].y : xq[m][kk >> 1].x;
                        ffma2(acc[m][0], xh, wq[kk].x);
                        ffma2(acc[m][1], xh, wq[kk].y);
                    }
                }
            };
            loadx(xA, 0); loadw(wA, KW);
#pragma unroll 1
            for (int k = 0; k < 64; k += 8) {
                loadx(xB, k + 4); loadw(wB, KW + k + 4);
                chunk(xA, wA);
                if (k + 8 < 64) { loadx(xA, k + 8); loadw(wA, KW + k + 8); }
                chunk(xB, wB);
            }
        }

        bar_grp(sg);                         // B: h reads done

#pragma unroll
        for (int m = 0; m < 8; m++) {
            float zi, zf, zg, zo;
            unpack2(acc[m][0], zi, zf);
            unpack2(acc[m][1], zg, zo);
            float c = sigf(zf) * cst[m] + sigf(zi) * mytanh(zg);
            cst[m] = c;
            float hv = sigf(zo) * mytanh(c);

            int s = sg * 8 + m;
            sH2[s * 64 + hid] = pack2(hv, hv);

            int q = s0 + s;
            int b = q >> 7, j = q & 127;
            out[((size_t)((b * 128 + j) * 128 + t)) * 128 + dir * 64 + hid] = hv;
        }
    }
}

extern "C" void kernel_launch(void* const* d_in, const int* in_sizes, int n_in,
                              void* d_out, int out_size)
{
    const float* inputs = (const float*)d_in[0];
    const float* W_ud = (const float*)d_in[1];
    const float* U_ud = (const float*)d_in[2];
    const float* b_ud = (const float*)d_in[3];
    const float* W_du = (const float*)d_in[4];
    const float* U_du = (const float*)d_in[5];
    const float* b_du = (const float*)d_in[6];
    const float* W_lr = (const float*)d_in[7];
    const float* U_lr = (const float*)d_in[8];
    const float* b_lr = (const float*)d_in[9];
    const float* W_rl = (const float*)d_in[10];
    const float* U_rl = (const float*)d_in[11];
    const float* b_rl = (const float*)d_in[12];

    ull* vbuf = nullptr;
    cudaGetSymbolAddress((void**)&vbuf, g_v2);

    size_t smem_v = (size_t)80 * NGC * 4 + (size_t)NSEQ * 80 * 8 + NGC * 4;   // 103,424
    size_t smem_h = (size_t)192 * NGC * 4 + (size_t)NSEQ * 64 * 8 + NGC * 4;  // 214,016

    cudaFuncSetAttribute(renet_vert,  cudaFuncAttributeMaxDynamicSharedMemorySize, (int)smem_v);
    cudaFuncSetAttribute(renet_horiz, cudaFuncAttributeMaxDynamicSharedMemorySize, (int)smem_h);

    renet_vert<<<128, 256, smem_v>>>(W_ud, U_ud, b_ud, W_du, U_du, b_du,
                                     inputs, vbuf);
    renet_horiz<<<128, 256, smem_h>>>(W_lr, U_lr, b_lr, W_rl, U_rl, b_rl,
                                      vbuf, (float*)d_out);
}

// round 15
// speedup vs baseline: 1.1140x; 1.1140x over previous
#include <cuda_runtime.h>

// ReNet layer, R14: warp-specialized horizontal pass.
//   Per 8-seq group: 1 X-warp (non-serial x@W, K=128, full 256 cols, reads v
//   from gmem + W from smem, computes step t+1 during step t) + 1 H-warp
//   (serial h@U K=64 from smem + gates). z-partials handed off via a gmem
//   ring (same-SM L1 coherent, membar.cta) with 64-thread named barriers.
//   Each SMSP = 1X + 1H: X fills fma-pipe gaps whenever H stalls on the
//   recurrence chain. Full-width lanes: lane owns hid pair (2l,2l+1) x 4
//   gates; weight layout pc = h*4 + g -> conflict-free LDS.128 pairs.
// Vertical pass: R10's proven kernel (512 thr, M=4) verbatim.

#define HIDN 64
#define NGC  256
#define BN   16
#define SJ   128
#define NSEQ 32

typedef unsigned long long ull;

__device__ float g_v[BN * SJ * SJ * 2 * HIDN];     // vertical output [B][J][I][128]
__device__ float g_ring[128 * NSEQ * NGC];         // z-partial ring, 4 MB

__device__ __forceinline__ ull pack2(float lo, float hi) {
    ull r; asm("mov.b64 %0, {%1, %2};" : "=l"(r) : "f"(lo), "f"(hi)); return r;
}
__device__ __forceinline__ void unpack2(ull v, float& lo, float& hi) {
    asm("mov.b64 {%0, %1}, %2;" : "=f"(lo), "=f"(hi) : "l"(v));
}
__device__ __forceinline__ void ffma2(ull& d, ull a, ull b) {
    asm("fma.rn.f32x2 %0, %1, %2, %0;" : "+l"(d) : "l"(a), "l"(b));
}
__device__ __forceinline__ ull addf2(ull a, ull b) {
    ull r; asm("add.rn.f32x2 %0, %1, %2;" : "=l"(r) : "l"(a), "l"(b)); return r;
}
__device__ __forceinline__ float sigf(float x)   { return 1.0f / (1.0f + __expf(-x)); }
__device__ __forceinline__ float mytanh(float x) { return 1.0f - 2.0f / (__expf(2.0f * x) + 1.0f); }

// ===========================================================================
// VERTICAL: R10 kernel verbatim (512 thr = 8 seq-groups x 2 hid-halves, M=4)
// ===========================================================================
#define VTHR 512
#define MSEQ 4

__device__ __forceinline__ void bar_grp8(int sg) {
    asm volatile("bar.sync %0, 64;" :: "r"(sg + 1) : "memory");
}

__global__ void __launch_bounds__(VTHR, 1)
renet_vert(const float* __restrict__ W0, const float* __restrict__ U0, const float* __restrict__ b0,
           const float* __restrict__ W1, const float* __restrict__ U1, const float* __restrict__ b1,
           const float* __restrict__ src, float* __restrict__ dst)
{
    constexpr int DIN = 12;
    constexpr int K  = DIN + HIDN;
    constexpr int KP = (K + 7) & ~7;          // 80
    extern __shared__ float sm[];
    float* sWU = sm;                   // [KP][NGC]
    float* sXH = sm + KP * NGC;        // [NSEQ][KP]
    float* sB  = sXH + NSEQ * KP;      // [NGC]

    const int dir  = blockIdx.x >> 6;
    const int s0   = (blockIdx.x & 63) * NSEQ;
    const int tid  = threadIdx.x;
    const int lane = tid & 31;
    const int wid  = tid >> 5;
    const int hh   = wid & 1;
    const int sg   = wid >> 1;
    const int ptid = tid & 63;
    const int hid  = hh * 32 + lane;

    const float* W  = dir ? W1 : W0;
    const float* U  = dir ? U1 : U0;
    const float* bb = dir ? b1 : b0;

    for (int idx = tid; idx < KP * NGC; idx += VTHR) {
        int k = idx >> 8, c = idx & 255;
        int g = c >> 6, h = c & 63;
        int pc = (h >> 5) * 128 + (h & 31) * 4 + g;
        float v = (k < DIN) ? W[k * NGC + c]
                 : (k < K)  ? U[(k - DIN) * NGC + c] : 0.0f;
        sWU[k * NGC + pc] = v;
    }
    for (int idx = tid; idx < NGC; idx += VTHR) sB[idx] = bb[idx];
    for (int idx = tid; idx < NSEQ * (KP - DIN); idx += VTHR) {
        int s = idx / (KP - DIN), o = idx % (KP - DIN);
        sXH[s * KP + DIN + o] = 0.0f;
    }
    __syncthreads();

    ull binit[2];
    binit[0] = pack2(sB[0 * HIDN + hid], sB[1 * HIDN + hid]);
    binit[1] = pack2(sB[2 * HIDN + hid], sB[3 * HIDN + hid]);

    float cst[MSEQ];
#pragma unroll
    for (int p = 0; p < MSEQ; p++) cst[p] = 0.0f;

    auto stage_x = [&](int t) {
        const int jin = dir ? (SJ - 1 - t) : t;
        for (int e = ptid; e < MSEQ * 12; e += 64) {
            int sl = e / 12, d = e - sl * 12;
            int q = s0 + sg * MSEQ + sl;
            int b = q >> 7, i = q & 127;
            int pr = d / 6, rm = d - pr * 6;
            int pc = rm / 3, ch = rm - pc * 3;
            sXH[(sg * MSEQ + sl) * KP + d] =
                src[((b * 256 + (2 * jin + pr)) * 256 + (2 * i + pc)) * 3 + ch];
        }
    };

    stage_x(0);

    const float* xbase = sXH + (sg * MSEQ) * KP;
    const float* wbase = sWU + hh * 128 + lane * 4;

    for (int t = 0; t < SJ; t++) {
        bar_grp8(sg);                          // A: x_t staged, h_{t-1} visible

        ull acc[MSEQ][2];
#pragma unroll
        for (int m = 0; m < MSEQ; m++) { acc[m][0] = binit[0]; acc[m][1] = binit[1]; }

        float4 xA[MSEQ], xB[MSEQ];
        ulonglong2 wA[4], wB[4];

        auto loadx = [&](float4* xq, int k) {
#pragma unroll
            for (int m = 0; m < MSEQ; m++) xq[m] = *(const float4*)&xbase[m * KP + k];
        };
        auto loadw = [&](ulonglong2* wq, int k) {
#pragma unroll
            for (int kk = 0; kk < 4; kk++)
                wq[kk] = *(const ulonglong2*)(wbase + (k + kk) * NGC);
        };
        auto chunk = [&](const float4* xq, const ulonglong2* wq) {
#pragma unroll
            for (int kk = 0; kk < 4; kk++) {
#pragma unroll
                for (int m = 0; m < MSEQ; m++) {
                    float a = ((const float*)&xq[m])[kk];
                    ull a2 = pack2(a, a);
                    ffma2(acc[m][0], a2, wq[kk].x);
                    ffma2(acc[m][1], a2, wq[kk].y);
                }
            }
        };

        loadx(xA, 0); loadw(wA, 0);
#pragma unroll 1
        for (int k = 0; k < KP; k += 8) {
            loadx(xB, k + 4); loadw(wB, k + 4);
            chunk(xA, wA);
            if (k + 8 < KP) { loadx(xA, k + 8); loadw(wA, k + 8); }
            chunk(xB, wB);
        }

        bar_grp8(sg);                          // B: group's reads of sXH done

#pragma unroll
        for (int m = 0; m < MSEQ; m++) {
            float zi, zf, zg, zo;
            unpack2(acc[m][0], zi, zf);
            unpack2(acc[m][1], zg, zo);
            float c = sigf(zf) * cst[m] + sigf(zi) * mytanh(zg);
            cst[m] = c;
            float hv = sigf(zo) * mytanh(c);

            int s = sg * MSEQ + m;
            sXH[s * KP + DIN + hid] = hv;

            int q = s0 + s;
            int b = q >> 7, w = q & 127;
            dst[((size_t)((b * 128 + t) * 128 + w)) * 128 + dir * 64 + hid] = hv;
        }

        if (t + 1 < SJ) stage_x(t + 1);
    }
}

// ===========================================================================
// HORIZONTAL: warp-specialized X (x@W, K=128, non-serial) / H (h@U + gates)
// 256 thr = 8 warps: wid 0..3 = H-warps of groups 0..3, wid 4..7 = X-warps.
// SMSP i gets warps {i (H), i+4 (X)}.
// ===========================================================================
__global__ void __launch_bounds__(256, 1)
renet_horiz(const float* __restrict__ W0, const float* __restrict__ U0, const float* __restrict__ b0,
            const float* __restrict__ W1, const float* __restrict__ U1, const float* __restrict__ b1,
            const float* __restrict__ vin, float* __restrict__ out)
{
    constexpr int KW = 128, KT = 192;
    extern __shared__ float sm[];
    float* sWU = sm;                 // [192][256], pc = h*4 + g
    float* sH  = sm + KT * NGC;      // [NSEQ][64] h state

    const int dir  = blockIdx.x >> 6;
    const int s0   = (blockIdx.x & 63) * NSEQ;
    const int tid  = threadIdx.x;
    const int lane = tid & 31;
    const int wid  = tid >> 5;
    const int sg   = wid & 3;                 // group: 8 seqs
    const bool isX = wid >= 4;
    const int h0   = 2 * lane;                // lane's hid pair

    const float* W  = dir ? W1 : W0;
    const float* U  = dir ? U1 : U0;
    const float* bb = dir ? b1 : b0;

    // weight layout: sWU[k][h*4 + g] = orig[k][g*64 + h]
    // lane reads cols [lane*8, lane*8+8): (i,f,g,o)h0, (i,f,g,o)h0+1 -> 2x LDS.128
    for (int idx = tid; idx < KT * NGC; idx += 256) {
        int k = idx >> 8, c = idx & 255;
        int pc = (c & 63) * 4 + (c >> 6);
        float v = (k < KW) ? W[k * NGC + c] : U[(k - KW) * NGC + c];
        sWU[k * NGC + pc] = v;
    }
    for (int idx = tid; idx < NSEQ * 64; idx += 256) sH[idx] = 0.0f;
    __syncthreads();

    const int q0 = s0 + sg * 8;               // group's 8 consecutive seqs (same b)
    const int bq = q0 >> 7, j0 = q0 & 127;
    const float* gx   = vin + ((size_t)(bq * 128 + j0)) * 128 * 128;
    float*       ring = g_ring + ((size_t)blockIdx.x * NSEQ + sg * 8) * NGC;
    const float* wl   = sWU + lane * 8;
    const float* hrow = sH + (sg * 8) * 64;

    auto barA = [&] { asm volatile("bar.sync %0, 64;" :: "r"(1 + sg) : "memory"); };
    auto barB = [&] { asm volatile("bar.sync %0, 64;" :: "r"(5 + sg) : "memory"); };

    if (isX) {
        // ------------------ X-warp: z-partial = bias + x @ W, K=128 --------
        ull binit[4];
        binit[0] = pack2(bb[0 * 64 + h0],     bb[1 * 64 + h0]);
        binit[1] = pack2(bb[2 * 64 + h0],     bb[3 * 64 + h0]);
        binit[2] = pack2(bb[0 * 64 + h0 + 1], bb[1 * 64 + h0 + 1]);
        binit[3] = pack2(bb[2 * 64 + h0 + 1], bb[3 * 64 + h0 + 1]);

        ull acc[8][4];
        auto computeX = [&](int tt) {
            const int i = dir ? (SJ - 1 - tt) : tt;
            const float* xp = gx + (size_t)i * 128;
#pragma unroll
            for (int m = 0; m < 8; m++) {
                acc[m][0] = binit[0]; acc[m][1] = binit[1];
                acc[m][2] = binit[2]; acc[m][3] = binit[3];
            }
            float4 xA[8], xB[8];
            ulonglong2 wA[4][2], wB[4][2];
            auto loadx = [&](float4* xq, int k) {
#pragma unroll
                for (int m = 0; m < 8; m++)
                    xq[m] = *(const float4*)(xp + (size_t)m * 16384 + k);
            };
            auto loadw = [&](ulonglong2 (*wq)[2], int k) {
#pragma unroll
                for (int kk = 0; kk < 4; kk++) {
                    wq[kk][0] = *(const ulonglong2*)(wl + (k + kk) * NGC);
                    wq[kk][1] = *(const ulonglong2*)(wl + (k + kk) * NGC + 4);
                }
            };
            auto chunk = [&](const float4* xq, const ulonglong2 (*wq)[2]) {
#pragma unroll
                for (int kk = 0; kk < 4; kk++) {
#pragma unroll
                    for (int m = 0; m < 8; m++) {
                        float a = ((const float*)&xq[m])[kk];
                        ull a2 = pack2(a, a);
                        ffma2(acc[m][0], a2, wq[kk][0].x);
                        ffma2(acc[m][1], a2, wq[kk][0].y);
                        ffma2(acc[m][2], a2, wq[kk][1].x);
                        ffma2(acc[m][3], a2, wq[kk][1].y);
                    }
                }
            };
            loadx(xA, 0); loadw(wA, 0);
#pragma unroll 1
            for (int k = 0; k < KW; k += 8) {
                loadx(xB, k + 4); loadw(wB, k + 4);
                chunk(xA, wA);
                if (k + 8 < KW) { loadx(xA, k + 8); loadw(wA, k + 8); }
                chunk(xB, wB);
            }
        };
        auto storeX = [&] {
#pragma unroll
            for (int m = 0; m < 8; m++) {
                ulonglong2 v0; v0.x = acc[m][0]; v0.y = acc[m][1];
                ulonglong2 v1; v1.x = acc[m][2]; v1.y = acc[m][3];
                *(ulonglong2*)(ring + m * NGC + lane * 8)     = v0;
                *(ulonglong2*)(ring + m * NGC + lane * 8 + 4) = v1;
            }
            asm volatile("membar.cta;" ::: "memory");
        };

        computeX(0); storeX();
        barA();                                // ring(0) visible
        for (int t = 0; t < SJ; t++) {
            if (t + 1 < SJ) computeX(t + 1);
            barB();                            // H finished reading ring(t)
            if (t + 1 < SJ) storeX();
            barA();                            // ring(t+1) visible
        }
    } else {
        // ------------------ H-warp: z += h @ U (K=64), gates, h update -----
        float cst[16];
#pragma unroll
        for (int p = 0; p < 16; p++) cst[p] = 0.0f;

        barA();                                // ring(0) ready
        for (int t = 0; t < SJ; t++) {
            // issue ring loads early; consume after the h-GEMM
            ulonglong2 r0[8], r1[8];
#pragma unroll
            for (int m = 0; m < 8; m++) {
                r0[m] = *(const ulonglong2*)(ring + m * NGC + lane * 8);
                r1[m] = *(const ulonglong2*)(ring + m * NGC + lane * 8 + 4);
            }

            ull acc[8][4];
#pragma unroll
            for (int m = 0; m < 8; m++) {
                acc[m][0] = 0ull; acc[m][1] = 0ull; acc[m][2] = 0ull; acc[m][3] = 0ull;
            }

            float4 xA[8], xB[8];
            ulonglong2 wA[4][2], wB[4][2];
            auto loadx = [&](float4* xq, int k) {
#pragma unroll
                for (int m = 0; m < 8; m++)
                    xq[m] = *(const float4*)(hrow + m * 64 + k);
            };
            auto loadw = [&](ulonglong2 (*wq)[2], int k) {
#pragma unroll
                for (int kk = 0; kk < 4; kk++) {
                    wq[kk][0] = *(const ulonglong2*)(wl + (KW + k + kk) * NGC);
                    wq[kk][1] = *(const ulonglong2*)(wl + (KW + k + kk) * NGC + 4);
                }
            };
            auto chunk = [&](const float4* xq, const ulonglong2 (*wq)[2]) {
#pragma unroll
                for (int kk = 0; kk < 4; kk++) {
#pragma unroll
                    for (int m = 0; m < 8; m++) {
                        float a = ((const float*)&xq[m])[kk];
                        ull a2 = pack2(a, a);
                        ffma2(acc[m][0], a2, wq[kk][0].x);
                        ffma2(acc[m][1], a2, wq[kk][0].y);
                        ffma2(acc[m][2], a2, wq[kk][1].x);
                        ffma2(acc[m][3], a2, wq[kk][1].y);
                    }
                }
            };
            loadx(xA, 0); loadw(wA, 0);
#pragma unroll 1
            for (int k = 0; k < 64; k += 8) {
                loadx(xB, k + 4); loadw(wB, k + 4);
                chunk(xA, wA);
                if (k + 8 < 64) { loadx(xA, k + 8); loadw(wA, k + 8); }
                chunk(xB, wB);
            }

            // fold in the x-part partials (bias already inside)
#pragma unroll
            for (int m = 0; m < 8; m++) {
                acc[m][0] = addf2(acc[m][0], r0[m].x);
                acc[m][1] = addf2(acc[m][1], r0[m].y);
                acc[m][2] = addf2(acc[m][2], r1[m].x);
                acc[m][3] = addf2(acc[m][3], r1[m].y);
            }

            barB();                            // ring(t) consumed; X may overwrite

#pragma unroll
            for (int m = 0; m < 8; m++) {
                float zi0, zf0, zg0, zo0, zi1, zf1, zg1, zo1;
                unpack2(acc[m][0], zi0, zf0);
                unpack2(acc[m][1], zg0, zo0);
                unpack2(acc[m][2], zi1, zf1);
                unpack2(acc[m][3], zg1, zo1);
                float c0 = sigf(zf0) * cst[2 * m]     + sigf(zi0) * mytanh(zg0);
                float c1 = sigf(zf1) * cst[2 * m + 1] + sigf(zi1) * mytanh(zg1);
                cst[2 * m] = c0; cst[2 * m + 1] = c1;
                float hv0 = sigf(zo0) * mytanh(c0);
                float hv1 = sigf(zo1) * mytanh(c1);

                *(float2*)&sH[(sg * 8 + m) * 64 + h0] = make_float2(hv0, hv1);

                int q = q0 + m;
                int b = q >> 7, j = q & 127;
                *(float2*)&out[((size_t)((b * 128 + j) * 128 + t)) * 128 + dir * 64 + h0]
                    = make_float2(hv0, hv1);
            }

            barA();                            // h(t) + ring(t+1) ready
        }
    }
}

extern "C" void kernel_launch(void* const* d_in, const int* in_sizes, int n_in,
                              void* d_out, int out_size)
{
    const float* inputs = (const float*)d_in[0];
    const float* W_ud = (const float*)d_in[1];
    const float* U_ud = (const float*)d_in[2];
    const float* b_ud = (const float*)d_in[3];
    const float* W_du = (const float*)d_in[4];
    const float* U_du = (const float*)d_in[5];
    const float* b_du = (const float*)d_in[6];
    const float* W_lr = (const float*)d_in[7];
    const float* U_lr = (const float*)d_in[8];
    const float* b_lr = (const float*)d_in[9];
    const float* W_rl = (const float*)d_in[10];
    const float* U_rl = (const float*)d_in[11];
    const float* b_rl = (const float*)d_in[12];

    float* vbuf = nullptr;
    cudaGetSymbolAddress((void**)&vbuf, g_v);

    size_t smem_v = (size_t)(80 * NGC + NSEQ * 80 + NGC) * sizeof(float);   //  93,184
    size_t smem_h = (size_t)(192 * NGC + NSEQ * 64) * sizeof(float);        // 204,800

    cudaFuncSetAttribute(renet_vert,  cudaFuncAttributeMaxDynamicSharedMemorySize, (int)smem_v);
    cudaFuncSetAttribute(renet_horiz, cudaFuncAttributeMaxDynamicSharedMemorySize, (int)smem_h);

    renet_vert<<<128, VTHR, smem_v>>>(W_ud, U_ud, b_ud, W_du, U_du, b_du,
                                      inputs, vbuf);
    renet_horiz<<<128, 256, smem_h>>>(W_lr, U_lr, b_lr, W_rl, U_rl, b_rl,
                                      vbuf, (float*)d_out);
}

// round 16
// speedup vs baseline: 1.5718x; 1.4110x over previous
#include <cuda_runtime.h>

// ReNet layer, R15: in-smem warp-specialized horizontal pass.
//   512 thr = 16 warps = 4 seq-groups(sg) x roles {A0,A1,B0,B1}; wid = role*4+sg
//   so SMSP == sg (each SMSP gets one group's 4 warps; FMA balanced).
//   A-warps (one per hid-half): z-partial += x @ W over k in [0,128) (all
//   non-serial columns), M=8, bias folded in. Never wait on h.
//   B-warps: z-partial += h @ U over k in [128,192), then merge A's partials
//   (2 rounds through the group's 4KB x-region), gates, h update, output.
//   A-warps stage x(t+1) during B's elementwise. 6 sg-local barriers/step.
// Vertical pass: R10's proven kernel (512 thr, M=4) verbatim.

#define HIDN 64
#define NGC  256
#define BN   16
#define SJ   128
#define NSEQ 32

typedef unsigned long long ull;

__device__ float g_v[BN * SJ * SJ * 2 * HIDN];     // vertical output [B][J][I][128]

__device__ __forceinline__ ull pack2(float lo, float hi) {
    ull r; asm("mov.b64 %0, {%1, %2};" : "=l"(r) : "f"(lo), "f"(hi)); return r;
}
__device__ __forceinline__ void unpack2(ull v, float& lo, float& hi) {
    asm("mov.b64 {%0, %1}, %2;" : "=f"(lo), "=f"(hi) : "l"(v));
}
__device__ __forceinline__ void ffma2(ull& d, ull a, ull b) {
    asm("fma.rn.f32x2 %0, %1, %2, %0;" : "+l"(d) : "l"(a), "l"(b));
}
__device__ __forceinline__ ull addf2(ull a, ull b) {
    ull r; asm("add.rn.f32x2 %0, %1, %2;" : "=l"(r) : "l"(a), "l"(b)); return r;
}
__device__ __forceinline__ float sigf(float x)   { return 1.0f / (1.0f + __expf(-x)); }
__device__ __forceinline__ float mytanh(float x) { return 1.0f - 2.0f / (__expf(2.0f * x) + 1.0f); }

// ===========================================================================
// VERTICAL: R10 kernel verbatim (512 thr = 8 seq-groups x 2 hid-halves, M=4)
// ===========================================================================
#define VTHR 512
#define MSEQ 4

__device__ __forceinline__ void bar_grp8(int sg) {
    asm volatile("bar.sync %0, 64;" :: "r"(sg + 1) : "memory");
}

__global__ void __launch_bounds__(VTHR, 1)
renet_vert(const float* __restrict__ W0, const float* __restrict__ U0, const float* __restrict__ b0,
           const float* __restrict__ W1, const float* __restrict__ U1, const float* __restrict__ b1,
           const float* __restrict__ src, float* __restrict__ dst)
{
    constexpr int DIN = 12;
    constexpr int K  = DIN + HIDN;
    constexpr int KP = (K + 7) & ~7;          // 80
    extern __shared__ float sm[];
    float* sWU = sm;                   // [KP][NGC]
    float* sXH = sm + KP * NGC;        // [NSEQ][KP]
    float* sB  = sXH + NSEQ * KP;      // [NGC]

    const int dir  = blockIdx.x >> 6;
    const int s0   = (blockIdx.x & 63) * NSEQ;
    const int tid  = threadIdx.x;
    const int lane = tid & 31;
    const int wid  = tid >> 5;
    const int hh   = wid & 1;
    const int sg   = wid >> 1;
    const int ptid = tid & 63;
    const int hid  = hh * 32 + lane;

    const float* W  = dir ? W1 : W0;
    const float* U  = dir ? U1 : U0;
    const float* bb = dir ? b1 : b0;

    for (int idx = tid; idx < KP * NGC; idx += VTHR) {
        int k = idx >> 8, c = idx & 255;
        int g = c >> 6, h = c & 63;
        int pc = (h >> 5) * 128 + (h & 31) * 4 + g;
        float v = (k < DIN) ? W[k * NGC + c]
                 : (k < K)  ? U[(k - DIN) * NGC + c] : 0.0f;
        sWU[k * NGC + pc] = v;
    }
    for (int idx = tid; idx < NGC; idx += VTHR) sB[idx] = bb[idx];
    for (int idx = tid; idx < NSEQ * (KP - DIN); idx += VTHR) {
        int s = idx / (KP - DIN), o = idx % (KP - DIN);
        sXH[s * KP + DIN + o] = 0.0f;
    }
    __syncthreads();

    ull binit[2];
    binit[0] = pack2(sB[0 * HIDN + hid], sB[1 * HIDN + hid]);
    binit[1] = pack2(sB[2 * HIDN + hid], sB[3 * HIDN + hid]);

    float cst[MSEQ];
#pragma unroll
    for (int p = 0; p < MSEQ; p++) cst[p] = 0.0f;

    auto stage_x = [&](int t) {
        const int jin = dir ? (SJ - 1 - t) : t;
        for (int e = ptid; e < MSEQ * 12; e += 64) {
            int sl = e / 12, d = e - sl * 12;
            int q = s0 + sg * MSEQ + sl;
            int b = q >> 7, i = q & 127;
            int pr = d / 6, rm = d - pr * 6;
            int pc = rm / 3, ch = rm - pc * 3;
            sXH[(sg * MSEQ + sl) * KP + d] =
                src[((b * 256 + (2 * jin + pr)) * 256 + (2 * i + pc)) * 3 + ch];
        }
    };

    stage_x(0);

    const float* xbase = sXH + (sg * MSEQ) * KP;
    const float* wbase = sWU + hh * 128 + lane * 4;

    for (int t = 0; t < SJ; t++) {
        bar_grp8(sg);                          // A: x_t staged, h_{t-1} visible

        ull acc[MSEQ][2];
#pragma unroll
        for (int m = 0; m < MSEQ; m++) { acc[m][0] = binit[0]; acc[m][1] = binit[1]; }

        float4 xA[MSEQ], xB[MSEQ];
        ulonglong2 wA[4], wB[4];

        auto loadx = [&](float4* xq, int k) {
#pragma unroll
            for (int m = 0; m < MSEQ; m++) xq[m] = *(const float4*)&xbase[m * KP + k];
        };
        auto loadw = [&](ulonglong2* wq, int k) {
#pragma unroll
            for (int kk = 0; kk < 4; kk++)
                wq[kk] = *(const ulonglong2*)(wbase + (k + kk) * NGC);
        };
        auto chunk = [&](const float4* xq, const ulonglong2* wq) {
#pragma unroll
            for (int kk = 0; kk < 4; kk++) {
#pragma unroll
                for (int m = 0; m < MSEQ; m++) {
                    float a = ((const float*)&xq[m])[kk];
                    ull a2 = pack2(a, a);
                    ffma2(acc[m][0], a2, wq[kk].x);
                    ffma2(acc[m][1], a2, wq[kk].y);
                }
            }
        };

        loadx(xA, 0); loadw(wA, 0);
#pragma unroll 1
        for (int k = 0; k < KP; k += 8) {
            loadx(xB, k + 4); loadw(wB, k + 4);
            chunk(xA, wA);
            if (k + 8 < KP) { loadx(xA, k + 8); loadw(wA, k + 8); }
            chunk(xB, wB);
        }

        bar_grp8(sg);                          // B: group's reads of sXH done

#pragma unroll
        for (int m = 0; m < MSEQ; m++) {
            float zi, zf, zg, zo;
            unpack2(acc[m][0], zi, zf);
            unpack2(acc[m][1], zg, zo);
            float c = sigf(zf) * cst[m] + sigf(zi) * mytanh(zg);
            cst[m] = c;
            float hv = sigf(zo) * mytanh(c);

            int s = sg * MSEQ + m;
            sXH[s * KP + DIN + hid] = hv;

            int q = s0 + s;
            int b = q >> 7, w = q & 127;
            dst[((size_t)((b * 128 + t) * 128 + w)) * 128 + dir * 64 + hid] = hv;
        }

        if (t + 1 < SJ) stage_x(t + 1);
    }
}

// ===========================================================================
// HORIZONTAL: in-smem warp specialization.
// wid = role*4 + sg; role 0,1 = A (x@W, hh=role), role 2,3 = B (h@U, hh=role-2)
// ===========================================================================
__global__ void __launch_bounds__(512, 1)
renet_horiz(const float* __restrict__ W0, const float* __restrict__ U0, const float* __restrict__ b0,
            const float* __restrict__ W1, const float* __restrict__ U1, const float* __restrict__ b1,
            const float* __restrict__ vin, float* __restrict__ out)
{
    constexpr int KW = 128, KT = 192;
    extern __shared__ float sm[];
    float* sW = sm;                  // [192][256] permuted weights (W ; U)
    float* sX = sm + KT * NGC;       // [32][128] x staging (+ partial exchange)
    float* sH = sX + NSEQ * 128;     // [32][64]  h state

    const int dir  = blockIdx.x >> 6;
    const int s0   = (blockIdx.x & 63) * NSEQ;
    const int tid  = threadIdx.x;
    const int lane = tid & 31;
    const int wid  = tid >> 5;
    const int sg   = wid & 3;                 // == SMSP id
    const int role = wid >> 2;
    const int hh   = role & 1;
    const bool isA = role < 2;
    const int hid  = hh * 32 + lane;
    const int xt   = hh * 32 + lane;          // 0..63 within the A or B pair

    const float* W  = dir ? W1 : W0;
    const float* U  = dir ? U1 : U0;
    const float* bb = dir ? b1 : b0;

    // weights permuted: sW[k][(h>>5)*128 + (h&31)*4 + g] = orig[k][g*64+h]
    for (int idx = tid; idx < KT * NGC; idx += 512) {
        int k = idx >> 8, c = idx & 255;
        int g = c >> 6, h = c & 63;
        int pc = (h >> 5) * 128 + (h & 31) * 4 + g;
        float v = (k < KW) ? W[k * NGC + c] : U[(k - KW) * NGC + c];
        sW[k * NGC + pc] = v;
    }
    for (int idx = tid; idx < NSEQ * 64; idx += 512) sH[idx] = 0.0f;
    // stage x(0): [32][128] floats = 1024 float4
    {
        const int i0 = dir ? (SJ - 1) : 0;
        for (int idx = tid; idx < 1024; idx += 512) {
            int s = idx >> 5, f4 = idx & 31;
            int q = s0 + s;
            int b = q >> 7, j = q & 127;
            *(float4*)&sX[s * 128 + f4 * 4] =
                *(const float4*)&vin[((size_t)((b * 128 + j) * 128 + i0)) * 128 + f4 * 4];
        }
    }
    __syncthreads();

    auto barS = [&] { asm volatile("bar.sync %0, 128;" :: "r"(1 + sg) : "memory"); };

    const float* wl    = sW + hh * 128 + lane * 4;
    const float* xrow  = sX + (sg * 8) * 128;
    ull*         xpart = (ull*)sX + (sg * 8) * 64;   // partial slots, 64 ull/row
    const float* hrow  = sH + (sg * 8) * 64;
    const int    q0    = s0 + sg * 8;
    const int    bq    = q0 >> 7, j0 = q0 & 127;

    // A-pair stages x(t+1) into its group's rows
    auto stage_x = [&](int t) {
        const int iin = dir ? (SJ - 1 - t) : t;
#pragma unroll
        for (int r = 0; r < 4; r++) {
            int idx = xt + 64 * r;             // 256 = 8 seq * 32 float4
            int sl = idx >> 5, f4 = idx & 31;
            *(float4*)&sX[(sg * 8 + sl) * 128 + f4 * 4] =
                *(const float4*)&vin[((size_t)((bq * 128 + j0 + sl) * 128 + iin)) * 128 + f4 * 4];
        }
    };

    if (isA) {
        // =================== A-warp: z += bias + x @ W, k in [0,128) =======
        ull binit[2];
        binit[0] = pack2(bb[0 * 64 + hid], bb[1 * 64 + hid]);
        binit[1] = pack2(bb[2 * 64 + hid], bb[3 * 64 + hid]);

        for (int t = 0; t < SJ; t++) {
            ull acc[8][2];
#pragma unroll
            for (int m = 0; m < 8; m++) { acc[m][0] = binit[0]; acc[m][1] = binit[1]; }

#pragma unroll 2
            for (int k = 0; k < KW; k += 4) {
                float4 xq[8];
                ulonglong2 wq[4];
#pragma unroll
                for (int m = 0; m < 8; m++) xq[m] = *(const float4*)&xrow[m * 128 + k];
#pragma unroll
                for (int kk = 0; kk < 4; kk++)
                    wq[kk] = *(const ulonglong2*)(wl + (k + kk) * NGC);
#pragma unroll
                for (int kk = 0; kk < 4; kk++) {
#pragma unroll
                    for (int m = 0; m < 8; m++) {
                        float a = ((const float*)&xq[m])[kk];
                        ull a2 = pack2(a, a);
                        ffma2(acc[m][0], a2, wq[kk].x);   // (zi, zf)
                        ffma2(acc[m][1], a2, wq[kk].y);   // (zg, zo)
                    }
                }
            }

            barS();                            // 1: all GEMMs done, x-region free
#pragma unroll
            for (int m = 0; m < 8; m++)        // round A: (zi,zf)
                xpart[m * 64 + hid] = acc[m][0];
            barS();                            // 2: round A visible
            barS();                            // 3: round A consumed
#pragma unroll
            for (int m = 0; m < 8; m++)        // round B: (zg,zo)
                xpart[m * 64 + hid] = acc[m][1];
            barS();                            // 4: round B visible
            barS();                            // 5: round B consumed, region free
            if (t + 1 < SJ) stage_x(t + 1);    // overlap B's elementwise
            barS();                            // 6: x(t+1) + h(t) ready
        }
    } else {
        // =================== B-warp: z += h @ U, k in [128,192); serial ====
        float cst[8];
#pragma unroll
        for (int p = 0; p < 8; p++) cst[p] = 0.0f;

        for (int t = 0; t < SJ; t++) {
            ull acc[8][2];
#pragma unroll
            for (int m = 0; m < 8; m++) { acc[m][0] = 0ull; acc[m][1] = 0ull; }

#pragma unroll 2
            for (int k = 0; k < 64; k += 4) {
                float4 xq[8];
                ulonglong2 wq[4];
#pragma unroll
                for (int m = 0; m < 8; m++) xq[m] = *(const float4*)&hrow[m * 64 + k];
#pragma unroll
                for (int kk = 0; kk < 4; kk++)
                    wq[kk] = *(const ulonglong2*)(wl + (KW + k + kk) * NGC);
#pragma unroll
                for (int kk = 0; kk < 4; kk++) {
#pragma unroll
                    for (int m = 0; m < 8; m++) {
                        float a = ((const float*)&xq[m])[kk];
                        ull a2 = pack2(a, a);
                        ffma2(acc[m][0], a2, wq[kk].x);
                        ffma2(acc[m][1], a2, wq[kk].y);
                    }
                }
            }

            barS();                            // 1: GEMMs done
            barS();                            // 2: round A visible
#pragma unroll
            for (int m = 0; m < 8; m++)
                acc[m][0] = addf2(acc[m][0], xpart[m * 64 + hid]);
            barS();                            // 3: round A consumed
            barS();                            // 4: round B visible
            ull rB[8];
#pragma unroll
            for (int m = 0; m < 8; m++) rB[m] = xpart[m * 64 + hid];
            barS();                            // 5: round B consumed

            // gates + state + h write + output (overlaps A's x staging)
#pragma unroll
            for (int m = 0; m < 8; m++) {
                ull zgo = addf2(acc[m][1], rB[m]);
                float zi, zf, zg, zo;
                unpack2(acc[m][0], zi, zf);
                unpack2(zgo, zg, zo);
                float c = sigf(zf) * cst[m] + sigf(zi) * mytanh(zg);
                cst[m] = c;
                float hv = sigf(zo) * mytanh(c);

                sH[(sg * 8 + m) * 64 + hid] = hv;

                int q = q0 + m;
                int b = q >> 7, j = q & 127;
                out[((size_t)((b * 128 + j) * 128 + t)) * 128 + dir * 64 + hid] = hv;
            }
            barS();                            // 6: x(t+1) + h(t) ready
        }
    }
}

extern "C" void kernel_launch(void* const* d_in, const int* in_sizes, int n_in,
                              void* d_out, int out_size)
{
    const float* inputs = (const float*)d_in[0];
    const float* W_ud = (const float*)d_in[1];
    const float* U_ud = (const float*)d_in[2];
    const float* b_ud = (const float*)d_in[3];
    const float* W_du = (const float*)d_in[4];
    const float* U_du = (const float*)d_in[5];
    const float* b_du = (const float*)d_in[6];
    const float* W_lr = (const float*)d_in[7];
    const float* U_lr = (const float*)d_in[8];
    const float* b_lr = (const float*)d_in[9];
    const float* W_rl = (const float*)d_in[10];
    const float* U_rl = (const float*)d_in[11];
    const float* b_rl = (const float*)d_in[12];

    float* vbuf = nullptr;
    cudaGetSymbolAddress((void**)&vbuf, g_v);

    size_t smem_v = (size_t)(80 * NGC + NSEQ * 80 + NGC) * sizeof(float);        //  93,184
    size_t smem_h = (size_t)(192 * NGC + NSEQ * 128 + NSEQ * 64) * sizeof(float); // 221,184

    cudaFuncSetAttribute(renet_vert,  cudaFuncAttributeMaxDynamicSharedMemorySize, (int)smem_v);
    cudaFuncSetAttribute(renet_horiz, cudaFuncAttributeMaxDynamicSharedMemorySize, (int)smem_h);

    renet_vert<<<128, VTHR, smem_v>>>(W_ud, U_ud, b_ud, W_du, U_du, b_du,
                                      inputs, vbuf);
    renet_horiz<<<128, 512, smem_h>>>(W_lr, U_lr, b_lr, W_rl, U_rl, b_rl,
                                      vbuf, (float*)d_out);
}

// round 17
// speedup vs baseline: 1.6047x; 1.0209x over previous
#include <cuda_runtime.h>

// ReNet layer, R16: 384-thread warp-specialized horizontal pass.
//   12 warps = 4 seq-groups(sg) x {A0, A1, B}; wid = role*4+sg so SMSP == sg.
//   A0/A1: z-partial = bias + x @ W over k in [0,128) for their hid-half,
//          M=8, register double-buffered (reg cap 170 at 384 thr).
//   B:     z-partial = h @ U over k in [128,192) for ALL 64 hid (lane =
//          hid-pair); h state is WARP-PRIVATE -> B's elementwise/h-update/
//          next-GEMM need no barriers at all.
//   Partials: 2 rounds through the group's 512-ull x-region; 4 group-wide
//   (96-thr) barriers + 2 A-pair (64-thr) barriers per step.
// Vertical pass: R10's proven kernel (512 thr, M=4) verbatim.

#define HIDN 64
#define NGC  256
#define BN   16
#define SJ   128
#define NSEQ 32

typedef unsigned long long ull;

__device__ float g_v[BN * SJ * SJ * 2 * HIDN];     // vertical output [B][J][I][128]

__device__ __forceinline__ ull pack2(float lo, float hi) {
    ull r; asm("mov.b64 %0, {%1, %2};" : "=l"(r) : "f"(lo), "f"(hi)); return r;
}
__device__ __forceinline__ void unpack2(ull v, float& lo, float& hi) {
    asm("mov.b64 {%0, %1}, %2;" : "=f"(lo), "=f"(hi) : "l"(v));
}
__device__ __forceinline__ void ffma2(ull& d, ull a, ull b) {
    asm("fma.rn.f32x2 %0, %1, %2, %0;" : "+l"(d) : "l"(a), "l"(b));
}
__device__ __forceinline__ ull addf2(ull a, ull b) {
    ull r; asm("add.rn.f32x2 %0, %1, %2;" : "=l"(r) : "l"(a), "l"(b)); return r;
}
__device__ __forceinline__ float sigf(float x)   { return 1.0f / (1.0f + __expf(-x)); }
__device__ __forceinline__ float mytanh(float x) { return 1.0f - 2.0f / (__expf(2.0f * x) + 1.0f); }

// ===========================================================================
// VERTICAL: R10 kernel verbatim (512 thr = 8 seq-groups x 2 hid-halves, M=4)
// ===========================================================================
#define VTHR 512
#define MSEQ 4

__device__ __forceinline__ void bar_grp8(int sg) {
    asm volatile("bar.sync %0, 64;" :: "r"(sg + 1) : "memory");
}

__global__ void __launch_bounds__(VTHR, 1)
renet_vert(const float* __restrict__ W0, const float* __restrict__ U0, const float* __restrict__ b0,
           const float* __restrict__ W1, const float* __restrict__ U1, const float* __restrict__ b1,
           const float* __restrict__ src, float* __restrict__ dst)
{
    constexpr int DIN = 12;
    constexpr int K  = DIN + HIDN;
    constexpr int KP = (K + 7) & ~7;          // 80
    extern __shared__ float sm[];
    float* sWU = sm;                   // [KP][NGC]
    float* sXH = sm + KP * NGC;        // [NSEQ][KP]
    float* sB  = sXH + NSEQ * KP;      // [NGC]

    const int dir  = blockIdx.x >> 6;
    const int s0   = (blockIdx.x & 63) * NSEQ;
    const int tid  = threadIdx.x;
    const int lane = tid & 31;
    const int wid  = tid >> 5;
    const int hh   = wid & 1;
    const int sg   = wid >> 1;
    const int ptid = tid & 63;
    const int hid  = hh * 32 + lane;

    const float* W  = dir ? W1 : W0;
    const float* U  = dir ? U1 : U0;
    const float* bb = dir ? b1 : b0;

    for (int idx = tid; idx < KP * NGC; idx += VTHR) {
        int k = idx >> 8, c = idx & 255;
        int g = c >> 6, h = c & 63;
        int pc = (h >> 5) * 128 + (h & 31) * 4 + g;
        float v = (k < DIN) ? W[k * NGC + c]
                 : (k < K)  ? U[(k - DIN) * NGC + c] : 0.0f;
        sWU[k * NGC + pc] = v;
    }
    for (int idx = tid; idx < NGC; idx += VTHR) sB[idx] = bb[idx];
    for (int idx = tid; idx < NSEQ * (KP - DIN); idx += VTHR) {
        int s = idx / (KP - DIN), o = idx % (KP - DIN);
        sXH[s * KP + DIN + o] = 0.0f;
    }
    __syncthreads();

    ull binit[2];
    binit[0] = pack2(sB[0 * HIDN + hid], sB[1 * HIDN + hid]);
    binit[1] = pack2(sB[2 * HIDN + hid], sB[3 * HIDN + hid]);

    float cst[MSEQ];
#pragma unroll
    for (int p = 0; p < MSEQ; p++) cst[p] = 0.0f;

    auto stage_x = [&](int t) {
        const int jin = dir ? (SJ - 1 - t) : t;
        for (int e = ptid; e < MSEQ * 12; e += 64) {
            int sl = e / 12, d = e - sl * 12;
            int q = s0 + sg * MSEQ + sl;
            int b = q >> 7, i = q & 127;
            int pr = d / 6, rm = d - pr * 6;
            int pc = rm / 3, ch = rm - pc * 3;
            sXH[(sg * MSEQ + sl) * KP + d] =
                src[((b * 256 + (2 * jin + pr)) * 256 + (2 * i + pc)) * 3 + ch];
        }
    };

    stage_x(0);

    const float* xbase = sXH + (sg * MSEQ) * KP;
    const float* wbase = sWU + hh * 128 + lane * 4;

    for (int t = 0; t < SJ; t++) {
        bar_grp8(sg);                          // A: x_t staged, h_{t-1} visible

        ull acc[MSEQ][2];
#pragma unroll
        for (int m = 0; m < MSEQ; m++) { acc[m][0] = binit[0]; acc[m][1] = binit[1]; }

        float4 xA[MSEQ], xB[MSEQ];
        ulonglong2 wA[4], wB[4];

        auto loadx = [&](float4* xq, int k) {
#pragma unroll
            for (int m = 0; m < MSEQ; m++) xq[m] = *(const float4*)&xbase[m * KP + k];
        };
        auto loadw = [&](ulonglong2* wq, int k) {
#pragma unroll
            for (int kk = 0; kk < 4; kk++)
                wq[kk] = *(const ulonglong2*)(wbase + (k + kk) * NGC);
        };
        auto chunk = [&](const float4* xq, const ulonglong2* wq) {
#pragma unroll
            for (int kk = 0; kk < 4; kk++) {
#pragma unroll
                for (int m = 0; m < MSEQ; m++) {
                    float a = ((const float*)&xq[m])[kk];
                    ull a2 = pack2(a, a);
                    ffma2(acc[m][0], a2, wq[kk].x);
                    ffma2(acc[m][1], a2, wq[kk].y);
                }
            }
        };

        loadx(xA, 0); loadw(wA, 0);
#pragma unroll 1
        for (int k = 0; k < KP; k += 8) {
            loadx(xB, k + 4); loadw(wB, k + 4);
            chunk(xA, wA);
            if (k + 8 < KP) { loadx(xA, k + 8); loadw(wA, k + 8); }
            chunk(xB, wB);
        }

        bar_grp8(sg);                          // B: group's reads of sXH done

#pragma unroll
        for (int m = 0; m < MSEQ; m++) {
            float zi, zf, zg, zo;
            unpack2(acc[m][0], zi, zf);
            unpack2(acc[m][1], zg, zo);
            float c = sigf(zf) * cst[m] + sigf(zi) * mytanh(zg);
            cst[m] = c;
            float hv = sigf(zo) * mytanh(c);

            int s = sg * MSEQ + m;
            sXH[s * KP + DIN + hid] = hv;

            int q = s0 + s;
            int b = q >> 7, w = q & 127;
            dst[((size_t)((b * 128 + t) * 128 + w)) * 128 + dir * 64 + hid] = hv;
        }

        if (t + 1 < SJ) stage_x(t + 1);
    }
}

// ===========================================================================
// HORIZONTAL: 384 thr, wid = role*4 + sg; role 0,1 = A (x@W hid-half),
// role 2 = B (h@U, full hid, lane = hid-pair, warp-private h state).
// ===========================================================================
__global__ void __launch_bounds__(384, 1)
renet_horiz(const float* __restrict__ W0, const float* __restrict__ U0, const float* __restrict__ b0,
            const float* __restrict__ W1, const float* __restrict__ U1, const float* __restrict__ b1,
            const float* __restrict__ vin, float* __restrict__ out)
{
    constexpr int KW = 128, KT = 192;
    extern __shared__ float sm[];
    float* sW = sm;                  // [192][256] permuted weights (W ; U)
    float* sX = sm + KT * NGC;       // [32][128] x staging + partial exchange
    float* sH = sX + NSEQ * 128;     // [32][64]  h state (B-warp private rows)

    const int dir  = blockIdx.x >> 6;
    const int s0   = (blockIdx.x & 63) * NSEQ;
    const int tid  = threadIdx.x;
    const int lane = tid & 31;
    const int wid  = tid >> 5;
    const int sg   = wid & 3;                 // == SMSP id
    const int role = wid >> 2;                // 0,1 = A-half; 2 = B
    const bool isA = role < 2;

    const float* W  = dir ? W1 : W0;
    const float* U  = dir ? U1 : U0;
    const float* bb = dir ? b1 : b0;

    // weights permuted: sW[k][(h>>5)*128 + (h&31)*4 + g] = orig[k][g*64+h]
    for (int idx = tid; idx < KT * NGC; idx += 384) {
        int k = idx >> 8, c = idx & 255;
        int g = c >> 6, h = c & 63;
        int pc = (h >> 5) * 128 + (h & 31) * 4 + g;
        float v = (k < KW) ? W[k * NGC + c] : U[(k - KW) * NGC + c];
        sW[k * NGC + pc] = v;
    }
    for (int idx = tid; idx < NSEQ * 64; idx += 384) sH[idx] = 0.0f;
    {   // stage x(0): 1024 float4
        const int i0 = dir ? (SJ - 1) : 0;
        for (int idx = tid; idx < 1024; idx += 384) {
            int s = idx >> 5, f4 = idx & 31;
            int q = s0 + s;
            int b = q >> 7, j = q & 127;
            *(float4*)&sX[s * 128 + f4 * 4] =
                *(const float4*)&vin[((size_t)((b * 128 + j) * 128 + i0)) * 128 + f4 * 4];
        }
    }
    __syncthreads();

    auto barG = [&] { asm volatile("bar.sync %0, 96;" :: "r"(1 + sg) : "memory"); };
    auto barA = [&] { asm volatile("bar.sync %0, 64;" :: "r"(5 + sg) : "memory"); };

    const float* xrow  = sX + (sg * 8) * 128;
    ull*         xpart = (ull*)sX + (sg * 8) * 64;   // 512 ull per group
    const float* hrow  = sH + (sg * 8) * 64;
    const int    q0    = s0 + sg * 8;
    const int    bq    = q0 >> 7, j0 = q0 & 127;

    if (isA) {
        // ================= A-warp: z = bias + x @ W, k in [0,128) ==========
        const int hh  = role;
        const int hid = hh * 32 + lane;
        const int xt  = hh * 32 + lane;        // 0..63 within the A pair
        const float* wl = sW + hh * 128 + lane * 4;

        ull binit[2];
        binit[0] = pack2(bb[0 * 64 + hid], bb[1 * 64 + hid]);
        binit[1] = pack2(bb[2 * 64 + hid], bb[3 * 64 + hid]);

        auto stage_x = [&](int t) {
            const int iin = dir ? (SJ - 1 - t) : t;
#pragma unroll
            for (int r = 0; r < 4; r++) {
                int idx = xt + 64 * r;         // 256 = 8 seq * 32 float4
                int sl = idx >> 5, f4 = idx & 31;
                *(float4*)&sX[(sg * 8 + sl) * 128 + f4 * 4] =
                    *(const float4*)&vin[((size_t)((bq * 128 + j0 + sl) * 128 + iin)) * 128 + f4 * 4];
            }
        };

        for (int t = 0; t < SJ; t++) {
            ull acc[8][2];
#pragma unroll
            for (int m = 0; m < 8; m++) { acc[m][0] = binit[0]; acc[m][1] = binit[1]; }

            float4 xA[8], xB[8];
            ulonglong2 wA[4], wB[4];
            auto loadx = [&](float4* xq, int k) {
#pragma unroll
                for (int m = 0; m < 8; m++) xq[m] = *(const float4*)&xrow[m * 128 + k];
            };
            auto loadw = [&](ulonglong2* wq, int k) {
#pragma unroll
                for (int kk = 0; kk < 4; kk++)
                    wq[kk] = *(const ulonglong2*)(wl + (k + kk) * NGC);
            };
            auto chunk = [&](const float4* xq, const ulonglong2* wq) {
#pragma unroll
                for (int kk = 0; kk < 4; kk++) {
#pragma unroll
                    for (int m = 0; m < 8; m++) {
                        float a = ((const float*)&xq[m])[kk];
                        ull a2 = pack2(a, a);
                        ffma2(acc[m][0], a2, wq[kk].x);   // (zi, zf)
                        ffma2(acc[m][1], a2, wq[kk].y);   // (zg, zo)
                    }
                }
            };

            loadx(xA, 0); loadw(wA, 0);
#pragma unroll 1
            for (int k = 0; k < KW; k += 8) {
                loadx(xB, k + 4); loadw(wB, k + 4);
                chunk(xA, wA);
                if (k + 8 < KW) { loadx(xA, k + 8); loadw(wA, k + 8); }
                chunk(xB, wB);
            }

            barA();                            // both A warps done reading x
#pragma unroll
            for (int m = 0; m < 8; m++)        // round A: (zi,zf)
                xpart[m * 64 + hid] = acc[m][0];
            barG();                            // G2: round A visible
            barG();                            // G3: round A consumed
#pragma unroll
            for (int m = 0; m < 8; m++)        // round B: (zg,zo)
                xpart[m * 64 + hid] = acc[m][1];
            barG();                            // G4: round B visible
            barG();                            // G5: round B consumed
            if (t + 1 < SJ) stage_x(t + 1);
            barA();                            // x(t+1) staged (pair-local)
        }
    } else {
        // ================= B-warp: z = h @ U, k in [128,192); lane=hid pair
        const int h0 = 2 * lane;
        const float* wl = sW + (h0 >> 5) * 128 + (h0 & 31) * 4;  // == 8*lane floats

        float cst[16];
#pragma unroll
        for (int p = 0; p < 16; p++) cst[p] = 0.0f;

        for (int t = 0; t < SJ; t++) {
            ull acc[8][4];                     // per seq: (zi,zf)h0,(zg,zo)h0,(zi,zf)h1,(zg,zo)h1
#pragma unroll
            for (int m = 0; m < 8; m++) {
                acc[m][0] = 0ull; acc[m][1] = 0ull; acc[m][2] = 0ull; acc[m][3] = 0ull;
            }

#pragma unroll 2
            for (int k = 0; k < 64; k += 4) {
                float4 xq[8];
                ulonglong2 wq[4][2];
#pragma unroll
                for (int m = 0; m < 8; m++) xq[m] = *(const float4*)&hrow[m * 64 + k];
#pragma unroll
                for (int kk = 0; kk < 4; kk++) {
                    wq[kk][0] = *(const ulonglong2*)(wl + (KW + k + kk) * NGC);
                    wq[kk][1] = *(const ulonglong2*)(wl + (KW + k + kk) * NGC + 4);
                }
#pragma unroll
                for (int kk = 0; kk < 4; kk++) {
#pragma unroll
                    for (int m = 0; m < 8; m++) {
                        float a = ((const float*)&xq[m])[kk];
                        ull a2 = pack2(a, a);
                        ffma2(acc[m][0], a2, wq[kk][0].x);
                        ffma2(acc[m][1], a2, wq[kk][0].y);
                        ffma2(acc[m][2], a2, wq[kk][1].x);
                        ffma2(acc[m][3], a2, wq[kk][1].y);
                    }
                }
            }

            barG();                            // G2: round A visible
#pragma unroll
            for (int m = 0; m < 8; m++) {      // (zi,zf) for h0 and h1
                ulonglong2 rA = *(const ulonglong2*)&xpart[m * 64 + h0];
                acc[m][0] = addf2(acc[m][0], rA.x);
                acc[m][2] = addf2(acc[m][2], rA.y);
            }
            barG();                            // G3: round A consumed
            barG();                            // G4: round B visible
            ulonglong2 rB[8];
#pragma unroll
            for (int m = 0; m < 8; m++) rB[m] = *(const ulonglong2*)&xpart[m * 64 + h0];
            barG();                            // G5: round B consumed

            // elementwise (no barriers needed after this point: h is warp-private)
#pragma unroll
            for (int m = 0; m < 8; m++) {
                ull zgo0 = addf2(acc[m][1], rB[m].x);
                ull zgo1 = addf2(acc[m][3], rB[m].y);
                float zi0, zf0, zg0, zo0, zi1, zf1, zg1, zo1;
                unpack2(acc[m][0], zi0, zf0);
                unpack2(zgo0, zg0, zo0);
                unpack2(acc[m][2], zi1, zf1);
                unpack2(zgo1, zg1, zo1);
                float c0 = sigf(zf0) * cst[2 * m]     + sigf(zi0) * mytanh(zg0);
                float c1 = sigf(zf1) * cst[2 * m + 1] + sigf(zi1) * mytanh(zg1);
                cst[2 * m] = c0; cst[2 * m + 1] = c1;
                float hv0 = sigf(zo0) * mytanh(c0);
                float hv1 = sigf(zo1) * mytanh(c1);

                *(float2*)&sH[(sg * 8 + m) * 64 + h0] = make_float2(hv0, hv1);

                int q = q0 + m;
                int b = q >> 7, j = q & 127;
                *(float2*)&out[((size_t)((b * 128 + j) * 128 + t)) * 128 + dir * 64 + h0]
                    = make_float2(hv0, hv1);
            }
        }
    }
}

extern "C" void kernel_launch(void* const* d_in, const int* in_sizes, int n_in,
                              void* d_out, int out_size)
{
    const float* inputs = (const float*)d_in[0];
    const float* W_ud = (const float*)d_in[1];
    const float* U_ud = (const float*)d_in[2];
    const float* b_ud = (const float*)d_in[3];
    const float* W_du = (const float*)d_in[4];
    const float* U_du = (const float*)d_in[5];
    const float* b_du = (const float*)d_in[6];
    const float* W_lr = (const float*)d_in[7];
    const float* U_lr = (const float*)d_in[8];
    const float* b_lr = (const float*)d_in[9];
    const float* W_rl = (const float*)d_in[10];
    const float* U_rl = (const float*)d_in[11];
    const float* b_rl = (const float*)d_in[12];

    float* vbuf = nullptr;
    cudaGetSymbolAddress((void**)&vbuf, g_v);

    size_t smem_v = (size_t)(80 * NGC + NSEQ * 80 + NGC) * sizeof(float);         //  93,184
    size_t smem_h = (size_t)(192 * NGC + NSEQ * 128 + NSEQ * 64) * sizeof(float); // 221,184

    cudaFuncSetAttribute(renet_vert,  cudaFuncAttributeMaxDynamicSharedMemorySize, (int)smem_v);
    cudaFuncSetAttribute(renet_horiz, cudaFuncAttributeMaxDynamicSharedMemorySize, (int)smem_h);

    renet_vert<<<128, VTHR, smem_v>>>(W_ud, U_ud, b_ud, W_du, U_du, b_du,
                                      inputs, vbuf);
    renet_horiz<<<128, 384, smem_h>>>(W_lr, U_lr, b_lr, W_rl, U_rl, b_rl,
                                      vbuf, (float*)d_out);
}